// round 4
// baseline (speedup 1.0000x reference)
#include <cuda_runtime.h>
#include <math.h>

// Problem constants
#define NB 4          // batch
#define NM 32         // masks (sam_masks[:,1:])
#define C2 1024       // channels of layer 2
#define P2 1024       // 32*32 pixels of layer 2
#define HMASK 512     // sam mask resolution

// Output layout: out0 | out1 | out2 concatenated
#define OFF1 16777216L   // 4*256*128*128
#define OFF2 25165824L   // OFF1 + 4*512*64*64
#define TOT  29360128L   // OFF2 + 4*1024*32*32
#define TOT4 (TOT/4)

// -------- scratch (device globals; no allocation allowed) --------
__device__ int   g_idx[NB*P2];          // mask id per sampled pixel, -1 if none
__device__ float g_cnt[NB*NM];          // pixels per mask
__device__ float g_mfpart[NB*4*NM*C2];  // pooling partials over 4 pixel-chunks
__device__ float g_mf0[NB*NM*C2];       // normalized mask features
__device__ float g_qpart[NB*8*NM*C2];   // q GEMM K-split partials
__device__ float g_q[NB*NM*C2];         // q = mf0 @ W^T + b
__device__ float g_qn[NB*NM];           // ||q_m||
__device__ float g_edge[NB*NM*NM];      // edge weights
__device__ float g_gp[NB*NM*C2];        // graph-attn output (unnormalized)
__device__ float g_gpsqp[NB*4*NM];      // per-ct-block partial sq-norms of gp
__device__ float g_scale[NB*NM];        // sigmoid(g)/max(||gp_m||,1e-12)

// -------- K1: per-batch sampled-pixel argmax-mask + counts --------
__global__ void k_idx(const int* __restrict__ sam) {
    int b = blockIdx.x;
    int p = threadIdx.x;                 // 1024 threads: p = y*32 + x
    int y = p >> 5, x = p & 31;
    long base = (long)b*33*HMASK*HMASK + (long)(y*16)*HMASK + (long)(x*16);
    int best = -1;
    #pragma unroll
    for (int m = 0; m < NM; m++) {
        int v = __ldg(sam + base + (long)(m+1)*HMASK*HMASK);
        if (v == 1) best = m;            // ascending overwrite == max
    }
    g_idx[b*P2 + p] = best;
    __shared__ int cnt[NM];
    if (p < NM) cnt[p] = 0;
    __syncthreads();
    if (best >= 0) atomicAdd(&cnt[best], 1);   // int atomics: deterministic
    __syncthreads();
    if (p < NM) g_cnt[b*NM + p] = (float)cnt[p];
}

// -------- K2: segmented pooling, per-thread private smem bins (conflict-free) --------
__global__ void k_mfpart(const float* __restrict__ feat2) {
    int b = blockIdx.x, ct = blockIdx.y, pc = blockIdx.z;
    int t = threadIdx.x;                 // 256 threads, thread = one channel
    int c = ct*256 + t;
    __shared__ float sbins[NM*256];      // sbins[m*256+t]: bank = t%32, no conflicts
    __shared__ int   sidx[256];
    #pragma unroll
    for (int m = 0; m < NM; m++) sbins[m*256 + t] = 0.f;
    sidx[t] = g_idx[b*P2 + pc*256 + t];
    __syncthreads();
    const float4* fp = (const float4*)(feat2 + ((long)b*C2 + c)*P2 + pc*256);
    #pragma unroll 4
    for (int i = 0; i < 64; i++) {
        float4 v = fp[i];
        int p0 = i*4;
        int m0 = sidx[p0+0], m1 = sidx[p0+1], m2 = sidx[p0+2], m3 = sidx[p0+3];
        if (m0 >= 0) sbins[m0*256 + t] += v.x;
        if (m1 >= 0) sbins[m1*256 + t] += v.y;
        if (m2 >= 0) sbins[m2*256 + t] += v.z;
        if (m3 >= 0) sbins[m3*256 + t] += v.w;
    }
    // bins are thread-private: no sync needed
    #pragma unroll
    for (int m = 0; m < NM; m++)
        g_mfpart[((b*4 + pc)*NM + m)*C2 + c] = sbins[m*256 + t];
}

// -------- K3: reduce partials, /(cnt+1e-5), row L2-normalize --------
__global__ void k_mf0() {
    int b = blockIdx.x, m = blockIdx.y, t = threadIdx.x;   // 256 threads
    float inv = 1.f / (g_cnt[b*NM + m] + 1e-5f);
    float r[4]; float sq = 0.f;
    #pragma unroll
    for (int j = 0; j < 4; j++) {
        int c = t + j*256;
        float v = 0.f;
        #pragma unroll
        for (int pc = 0; pc < 4; pc++)
            v += g_mfpart[((b*4 + pc)*NM + m)*C2 + c];
        r[j] = v * inv;
        sq += r[j]*r[j];
    }
    __shared__ float red[256];
    red[t] = sq; __syncthreads();
    for (int s = 128; s > 0; s >>= 1) { if (t < s) red[t] += red[t+s]; __syncthreads(); }
    float scale = 1.f / fmaxf(sqrtf(red[0]), 1e-12f);
    #pragma unroll
    for (int j = 0; j < 4; j++)
        g_mf0[(b*NM + m)*C2 + t + j*256] = r[j]*scale;
}

// -------- K4: q = mf0 @ W^T, K-split x8, 2 channels/thread --------
__global__ void k_qgemm(const float* __restrict__ W) {
    int b = blockIdx.x, ct = blockIdx.y, ks = blockIdx.z;
    int t = threadIdx.x;                 // 128 threads
    __shared__ float smf[NM*128];        // mf0[m][k-chunk], broadcast reads
    for (int i = t; i < NM*128; i += 128) {
        int m = i >> 7, k = i & 127;
        smf[i] = g_mf0[(b*NM + m)*C2 + ks*128 + k];
    }
    __syncthreads();
    int c0 = ct*256 + t, c1 = c0 + 128;
    const float4* w0 = (const float4*)(W + (long)c0*C2 + ks*128);
    const float4* w1 = (const float4*)(W + (long)c1*C2 + ks*128);
    float acc0[NM], acc1[NM];
    #pragma unroll
    for (int m = 0; m < NM; m++) { acc0[m] = 0.f; acc1[m] = 0.f; }
    #pragma unroll 2
    for (int k4 = 0; k4 < 32; k4++) {
        float4 a = w0[k4], bb = w1[k4];
        #pragma unroll
        for (int kk = 0; kk < 4; kk++) {
            float wa = ((const float*)&a)[kk];
            float wb = ((const float*)&bb)[kk];
            int kidx = k4*4 + kk;
            #pragma unroll
            for (int m = 0; m < NM; m++) {
                float mv = smf[m*128 + kidx];
                acc0[m] += mv*wa;
                acc1[m] += mv*wb;
            }
        }
    }
    #pragma unroll
    for (int m = 0; m < NM; m++) {
        g_qpart[((b*8 + ks)*NM + m)*C2 + c0] = acc0[m];
        g_qpart[((b*8 + ks)*NM + m)*C2 + c1] = acc1[m];
    }
}

// -------- K5: q = sum(K-splits) + bias; row norms --------
__global__ void k_qreduce(const float* __restrict__ bias) {
    int b = blockIdx.x, m = blockIdx.y, t = threadIdx.x;   // 256
    float r[4]; float sq = 0.f;
    #pragma unroll
    for (int j = 0; j < 4; j++) {
        int c = t + j*256;
        float v = bias[c];
        #pragma unroll
        for (int ks = 0; ks < 8; ks++)
            v += g_qpart[((b*8 + ks)*NM + m)*C2 + c];
        r[j] = v; sq += v*v;
        g_q[(b*NM + m)*C2 + c] = v;
    }
    __shared__ float red[256];
    red[t] = sq; __syncthreads();
    for (int s = 128; s > 0; s >>= 1) { if (t < s) red[t] += red[t+s]; __syncthreads(); }
    if (t == 0) g_qn[b*NM + m] = sqrtf(red[0]);
}

// -------- K6: sim row -> edge row (one block per (b, i)) --------
__global__ void k_simedge() {
    int b = blockIdx.x, i = blockIdx.y, t = threadIdx.x;   // 256
    int j = t >> 3, s = t & 7;
    const float4* qi = (const float4*)(g_q + (b*NM + i)*C2 + s*128);
    const float4* qj = (const float4*)(g_q + (b*NM + j)*C2 + s*128);
    float part = 0.f;
    #pragma unroll 8
    for (int k = 0; k < 32; k++) {
        float4 a = qi[k], bb = qj[k];
        part += a.x*bb.x + a.y*bb.y + a.z*bb.z + a.w*bb.w;
    }
    __shared__ float sd[NM*8];
    sd[j*8 + s] = part;
    __syncthreads();
    if (t < NM) {
        float d = 0.f;
        #pragma unroll
        for (int ss = 0; ss < 8; ss++) d += sd[t*8 + ss];
        float sim = d / (g_qn[b*NM + i]*g_qn[b*NM + t] + 1e-8f);
        float tot = sim;
        #pragma unroll
        for (int o = 16; o; o >>= 1) tot += __shfl_xor_sync(0xffffffffu, tot, o);
        g_edge[(b*NM + i)*NM + t] = sim / (tot + 1e-8f);
    }
}

// -------- K7: gp = edge @ q; deterministic block-partial sq-norms --------
__global__ void k_gp() {
    int b = blockIdx.x, ct = blockIdx.y, t = threadIdx.x;  // 256
    int c = ct*256 + t;
    __shared__ float se[NM*NM];
    for (int i = t; i < NM*NM; i += 256) se[i] = g_edge[b*NM*NM + i];
    __syncthreads();
    float acc[NM];
    #pragma unroll
    for (int m = 0; m < NM; m++) acc[m] = 0.f;
    #pragma unroll 4
    for (int n = 0; n < NM; n++) {
        float qv = g_q[(b*NM + n)*C2 + c];
        #pragma unroll
        for (int m = 0; m < NM; m++) acc[m] += se[m*NM + n]*qv;
    }
    __shared__ float sw[NM*8];
    int w = t >> 5, l = t & 31;
    #pragma unroll
    for (int m = 0; m < NM; m++) {
        g_gp[(b*NM + m)*C2 + c] = acc[m];
        float v = acc[m]*acc[m];
        #pragma unroll
        for (int o = 16; o; o >>= 1) v += __shfl_xor_sync(0xffffffffu, v, o);
        if (l == 0) sw[m*8 + w] = v;
    }
    __syncthreads();
    if (t < NM) {
        float s2 = 0.f;
        #pragma unroll
        for (int ww = 0; ww < 8; ww++) s2 += sw[t*8 + ww];
        g_gpsqp[(b*4 + ct)*NM + t] = s2;   // no atomics: fixed-order reduce later
    }
}

// -------- K8: per-(b,m) gate scale = sigmoid(g)/max(||gp||,1e-12) --------
__global__ void k_scale(const float* __restrict__ gate) {
    int i = threadIdx.x;                 // 128 = NB*NM
    if (i < NB*NM) {
        int b = i >> 5, m = i & 31;
        float s2 = 0.f;
        #pragma unroll
        for (int ct = 0; ct < 4; ct++) s2 += g_gpsqp[(b*4 + ct)*NM + m];
        float sg = 1.f / (1.f + expf(-gate[0]));
        g_scale[i] = sg / fmaxf(sqrtf(s2), 1e-12f);
    }
}

// -------- K9: copies (out0,out1) + out2 = feat2 + gather(mf_final) --------
__global__ void k_final(const float* __restrict__ f0,
                        const float* __restrict__ f1,
                        const float* __restrict__ f2,
                        float* __restrict__ out) {
    long i4 = (long)blockIdx.x*blockDim.x + threadIdx.x;
    if (i4 >= TOT4) return;
    float4* out4 = (float4*)out;
    if (i4 < OFF1/4) {                                   // out0 = feat0
        out4[i4] = ((const float4*)f0)[i4];
        return;
    }
    if (i4 < OFF2/4) {                                   // out1 = feat1
        out4[i4] = ((const float4*)f1)[i4 - OFF1/4];
        return;
    }
    long o4 = i4 - OFF2/4;                               // out2 region
    long o  = o4*4;
    int b   = (int)(o >> 20);                            // 1024*1024 per batch
    int rem = (int)(o & 1048575);
    int c   = rem >> 10;
    int p   = rem & 1023;                                // multiple of 4
    float4 v = ((const float4*)f2)[o4];
    int4 mm = *(const int4*)(g_idx + b*P2 + p);
    float* vv = (float*)&v;
    int mmv[4] = {mm.x, mm.y, mm.z, mm.w};
    #pragma unroll
    for (int j = 0; j < 4; j++) {
        int m = mmv[j];
        if (m >= 0) {
            int a = (b*NM + m)*C2 + c;
            vv[j] += g_mf0[a] + g_scale[b*NM + m]*g_gp[a];
        }
    }
    out4[i4] = v;
}

extern "C" void kernel_launch(void* const* d_in, const int* in_sizes, int n_in,
                              void* d_out, int out_size) {
    // Resolve inputs by unique element counts (robust to metadata ordering).
    const float* f0 = 0; const float* f1 = 0; const float* f2 = 0;
    const int* sam = 0; const float* W2 = 0; const float* b2 = 0;
    const float* g2 = 0;
    for (int i = 0; i < n_in; i++) {
        switch (in_sizes[i]) {
            case 16777216: f0  = (const float*)d_in[i]; break;  // 4*256*128*128
            case 8388608:  f1  = (const float*)d_in[i]; break;  // 4*512*64*64
            case 4194304:  f2  = (const float*)d_in[i]; break;  // 4*1024*32*32
            case 34603008: sam = (const int*)d_in[i];   break;  // 4*33*512*512
            case 1048576:  W2  = (const float*)d_in[i]; break;  // 1024*1024
            case 1024:     b2  = (const float*)d_in[i]; break;  // bias2
            case 1: if (!g2) g2 = (const float*)d_in[i]; break; // gates all equal
            default: break;
        }
    }
    float* out = (float*)d_out;

    k_idx    <<<NB, 1024>>>(sam);
    k_mfpart <<<dim3(NB,4,4), 256>>>(f2);
    k_mf0    <<<dim3(NB,NM), 256>>>();
    k_qgemm  <<<dim3(NB,4,8), 128>>>(W2);
    k_qreduce<<<dim3(NB,NM), 256>>>(b2);
    k_simedge<<<dim3(NB,NM), 256>>>();
    k_gp     <<<dim3(NB,4), 256>>>();
    k_scale  <<<1, 128>>>(g2);
    k_final  <<<(unsigned)(TOT4/256), 256>>>(f0, f1, f2, out);
}

// round 6
// speedup vs baseline: 1.0526x; 1.0526x over previous
#include <cuda_runtime.h>
#include <math.h>

// Problem constants
#define NB 4          // batch
#define NM 32         // masks (sam_masks[:,1:])
#define C2 1024       // channels of layer 2
#define P2 1024       // 32*32 pixels of layer 2
#define HMASK 512     // sam mask resolution
#define KS 16         // K-splits for q GEMM
#define KC 64         // K per split (KS*KC = 1024)

// Output layout: out0 | out1 | out2 concatenated
#define OFF1 16777216L   // 4*256*128*128
#define OFF2 25165824L   // OFF1 + 4*512*64*64
#define TOT  29360128L   // OFF2 + 4*1024*32*32
#define TOT4 (TOT/4)

// -------- scratch (device globals; no allocation allowed) --------
__device__ int   g_idx[NB*P2];           // mask id per sampled pixel, -1 if none
__device__ float g_mfpart[NB*4*NM*C2];   // pooling partials over 4 pixel-chunks
__device__ float g_mf0[NB*NM*C2];        // normalized mask features
__device__ float g_qpart[NB*KS*NM*C2];   // q GEMM K-split partials (8MB)
__device__ float g_q[NB*NM*C2];          // q = mf0 @ W^T + b
__device__ float g_qn[NB*NM];            // ||q_m||
__device__ float g_edge[NB*NM*NM];       // edge weights
__device__ float g_gp[NB*NM*C2];         // graph-attn output (unnormalized)
__device__ float g_gpsqp[NB*4*NM];       // per-ct-block partial sq-norms of gp
__device__ float g_scale[NB*NM];         // sigmoid(g)/max(||gp_m||,1e-12)

// -------- K1: argmax mask id; block = (b, one sampled row), smem atomicMax --------
// 128 blocks x 1024 threads: warp w -> mask m=w over 32 x-positions. No global
// pre-init needed; int shared atomics = deterministic.
__global__ void k_idx(const int* __restrict__ sam) {
    int b = blockIdx.x, y = blockIdx.y;      // y = sampled row (0..31)
    int t = threadIdx.x;                     // 1024: m = t>>5, x = t&31
    int m = t >> 5, x = t & 31;
    __shared__ int best[32];
    if (t < 32) best[t] = -1;
    __syncthreads();
    long off = ((long)b*33 + (m+1))*HMASK*HMASK + (long)(y*16)*HMASK + (long)(x*16);
    if (__ldg(sam + off) == 1)
        atomicMax(&best[x], m);
    __syncthreads();
    if (t < 32) g_idx[b*P2 + y*32 + t] = best[t];
}

// -------- K2: segmented pooling, per-thread private smem bins --------
__global__ void k_mfpart(const float* __restrict__ feat2) {
    int b = blockIdx.x, ct = blockIdx.y, pc = blockIdx.z;
    int t = threadIdx.x;                 // 256, thread = one channel
    int c = ct*256 + t;
    __shared__ float sbins[NM*256];      // [m*256+t]: bank = t%32, conflict-free
    __shared__ int   sidx[256];
    #pragma unroll
    for (int m = 0; m < NM; m++) sbins[m*256 + t] = 0.f;
    sidx[t] = g_idx[b*P2 + pc*256 + t];
    __syncthreads();
    const float4* fp = (const float4*)(feat2 + ((long)b*C2 + c)*P2 + pc*256);
    #pragma unroll 4
    for (int i = 0; i < 64; i++) {
        float4 v = fp[i];
        int p0 = i*4;
        int m0 = sidx[p0+0], m1 = sidx[p0+1], m2 = sidx[p0+2], m3 = sidx[p0+3];
        if (m0 >= 0) sbins[m0*256 + t] += v.x;
        if (m1 >= 0) sbins[m1*256 + t] += v.y;
        if (m2 >= 0) sbins[m2*256 + t] += v.z;
        if (m3 >= 0) sbins[m3*256 + t] += v.w;
    }
    #pragma unroll
    for (int m = 0; m < NM; m++)
        g_mfpart[((b*4 + pc)*NM + m)*C2 + c] = sbins[m*256 + t];
}

// -------- K3: count + reduce partials + /(cnt+1e-5) + L2-normalize --------
__global__ void k_mf0() {
    int b = blockIdx.x, m = blockIdx.y, t = threadIdx.x;   // 256
    __shared__ float red[256];
    const int* ip = g_idx + b*P2;
    int cnt = 0;
    #pragma unroll
    for (int j = 0; j < 4; j++) cnt += (ip[t + j*256] == m);
    red[t] = (float)cnt; __syncthreads();
    for (int s = 128; s > 0; s >>= 1) { if (t < s) red[t] += red[t+s]; __syncthreads(); }
    float inv = 1.f / (red[0] + 1e-5f);
    __syncthreads();
    float r[4]; float sq = 0.f;
    #pragma unroll
    for (int j = 0; j < 4; j++) {
        int c = t + j*256;
        float v = 0.f;
        #pragma unroll
        for (int pc = 0; pc < 4; pc++)
            v += g_mfpart[((b*4 + pc)*NM + m)*C2 + c];
        r[j] = v * inv;
        sq += r[j]*r[j];
    }
    red[t] = sq; __syncthreads();
    for (int s = 128; s > 0; s >>= 1) { if (t < s) red[t] += red[t+s]; __syncthreads(); }
    float scale = 1.f / fmaxf(sqrtf(red[0]), 1e-12f);
    #pragma unroll
    for (int j = 0; j < 4; j++)
        g_mf0[(b*NM + m)*C2 + t + j*256] = r[j]*scale;
}

// -------- K4: q = mf0 @ W^T. 4x4 register tile, smem-staged, K-split x16 --------
// grid (NB, 8 cblk, KS), 256 threads. Block covers 128 channels x 32 m x 64 K.
__global__ void k_qgemm(const float* __restrict__ W) {
    int b = blockIdx.x, cb = blockIdx.y, ks = blockIdx.z;
    int t = threadIdx.x;                       // 256
    __shared__ float sW[KC][128];              // [k][c]  32KB
    __shared__ float sM[KC][NM];               // [k][m]   8KB
    // stage W chunk transposed: 128c x 16 k4-groups = 2048 float4 tasks
    #pragma unroll
    for (int it = 0; it < 8; it++) {
        int task = it*256 + t;
        int c = task & 127, k4 = task >> 7;
        float4 w = *(const float4*)(W + ((long)(cb*128 + c))*C2 + ks*KC + k4*4);
        sW[k4*4+0][c] = w.x; sW[k4*4+1][c] = w.y;
        sW[k4*4+2][c] = w.z; sW[k4*4+3][c] = w.w;
    }
    // stage mf0 chunk transposed: 16 k4 x 32 m = 512 float4 tasks
    #pragma unroll
    for (int it = 0; it < 2; it++) {
        int task = it*256 + t;
        int m = task & 31, k4 = task >> 5;
        float4 v = *(const float4*)(g_mf0 + (b*NM + m)*C2 + ks*KC + k4*4);
        sM[k4*4+0][m] = v.x; sM[k4*4+1][m] = v.y;
        sM[k4*4+2][m] = v.z; sM[k4*4+3][m] = v.w;
    }
    __syncthreads();
    int cg = t & 31, mg = t >> 5;              // 32 c-groups x 8 m-groups
    int c0 = cg*4, m0 = mg*4;
    float acc[4][4];
    #pragma unroll
    for (int i = 0; i < 4; i++)
        #pragma unroll
        for (int j = 0; j < 4; j++) acc[i][j] = 0.f;
    #pragma unroll 4
    for (int k = 0; k < KC; k++) {
        float4 wv = *(const float4*)&sW[k][c0];   // contiguous LDS.128
        float4 mv = *(const float4*)&sM[k][m0];   // warp-uniform broadcast
        const float* wf = (const float*)&wv;
        const float* mf = (const float*)&mv;
        #pragma unroll
        for (int mi = 0; mi < 4; mi++)
            #pragma unroll
            for (int ci = 0; ci < 4; ci++)
                acc[mi][ci] += mf[mi]*wf[ci];
    }
    #pragma unroll
    for (int mi = 0; mi < 4; mi++) {
        float4 o = make_float4(acc[mi][0], acc[mi][1], acc[mi][2], acc[mi][3]);
        *(float4*)(g_qpart + ((long)(b*KS + ks)*NM + m0+mi)*C2 + cb*128 + c0) = o;
    }
}

// -------- K5: q = sum(K-splits) + bias; row norms --------
__global__ void k_qreduce(const float* __restrict__ bias) {
    int b = blockIdx.x, m = blockIdx.y, t = threadIdx.x;   // 256
    float r[4]; float sq = 0.f;
    #pragma unroll
    for (int j = 0; j < 4; j++) {
        int c = t + j*256;
        float v = bias[c];
        #pragma unroll
        for (int ks = 0; ks < KS; ks++)
            v += g_qpart[((long)(b*KS + ks)*NM + m)*C2 + c];
        r[j] = v; sq += v*v;
        g_q[(b*NM + m)*C2 + c] = v;
    }
    __shared__ float red[256];
    red[t] = sq; __syncthreads();
    for (int s = 128; s > 0; s >>= 1) { if (t < s) red[t] += red[t+s]; __syncthreads(); }
    if (t == 0) g_qn[b*NM + m] = sqrtf(red[0]);
}

// -------- K6: sim row -> edge row --------
__global__ void k_simedge() {
    int b = blockIdx.x, i = blockIdx.y, t = threadIdx.x;   // 256
    int j = t >> 3, s = t & 7;
    const float4* qi = (const float4*)(g_q + (b*NM + i)*C2 + s*128);
    const float4* qj = (const float4*)(g_q + (b*NM + j)*C2 + s*128);
    float part = 0.f;
    #pragma unroll 8
    for (int k = 0; k < 32; k++) {
        float4 a = qi[k], bb = qj[k];
        part += a.x*bb.x + a.y*bb.y + a.z*bb.z + a.w*bb.w;
    }
    __shared__ float sd[NM*8];
    sd[j*8 + s] = part;
    __syncthreads();
    if (t < NM) {
        float d = 0.f;
        #pragma unroll
        for (int ss = 0; ss < 8; ss++) d += sd[t*8 + ss];
        float sim = d / (g_qn[b*NM + i]*g_qn[b*NM + t] + 1e-8f);
        float tot = sim;
        #pragma unroll
        for (int o = 16; o; o >>= 1) tot += __shfl_xor_sync(0xffffffffu, tot, o);
        g_edge[(b*NM + i)*NM + t] = sim / (tot + 1e-8f);
    }
}

// -------- K7: gp = edge @ q; deterministic block-partial sq-norms --------
__global__ void k_gp() {
    int b = blockIdx.x, ct = blockIdx.y, t = threadIdx.x;  // 256
    int c = ct*256 + t;
    __shared__ float se[NM*NM];
    for (int i = t; i < NM*NM; i += 256) se[i] = g_edge[b*NM*NM + i];
    __syncthreads();
    float acc[NM];
    #pragma unroll
    for (int m = 0; m < NM; m++) acc[m] = 0.f;
    #pragma unroll 4
    for (int n = 0; n < NM; n++) {
        float qv = g_q[(b*NM + n)*C2 + c];
        #pragma unroll
        for (int m = 0; m < NM; m++) acc[m] += se[m*NM + n]*qv;
    }
    __shared__ float sw[NM*8];
    int w = t >> 5, l = t & 31;
    #pragma unroll
    for (int m = 0; m < NM; m++) {
        g_gp[(b*NM + m)*C2 + c] = acc[m];
        float v = acc[m]*acc[m];
        #pragma unroll
        for (int o = 16; o; o >>= 1) v += __shfl_xor_sync(0xffffffffu, v, o);
        if (l == 0) sw[m*8 + w] = v;
    }
    __syncthreads();
    if (t < NM) {
        float s2 = 0.f;
        #pragma unroll
        for (int ww = 0; ww < 8; ww++) s2 += sw[t*8 + ww];
        g_gpsqp[(b*4 + ct)*NM + t] = s2;
    }
}

// -------- K8: per-(b,m) gate scale --------
__global__ void k_scale(const float* __restrict__ gate) {
    int i = threadIdx.x;                 // 128 = NB*NM
    if (i < NB*NM) {
        int b = i >> 5, m = i & 31;
        float s2 = 0.f;
        #pragma unroll
        for (int ct = 0; ct < 4; ct++) s2 += g_gpsqp[(b*4 + ct)*NM + m];
        float sg = 1.f / (1.f + expf(-gate[0]));
        g_scale[i] = sg / fmaxf(sqrtf(s2), 1e-12f);
    }
}

// -------- K9: copies (out0,out1) + out2 = feat2 + gather(mf_final) --------
__global__ void k_final(const float* __restrict__ f0,
                        const float* __restrict__ f1,
                        const float* __restrict__ f2,
                        float* __restrict__ out) {
    long i4 = (long)blockIdx.x*256 + threadIdx.x;        // TOT4 exact multiple
    float4* out4 = (float4*)out;
    if (i4 < OFF1/4) {                                   // out0 = feat0
        out4[i4] = ((const float4*)f0)[i4];
        return;
    }
    if (i4 < OFF2/4) {                                   // out1 = feat1
        out4[i4] = ((const float4*)f1)[i4 - OFF1/4];
        return;
    }
    long o4 = i4 - OFF2/4;                               // out2 region
    int b   = (int)(o4 >> 18);                           // 262144 float4/batch
    int rem = (int)(o4 & 262143);
    int c   = rem >> 8;
    int p   = (rem & 255)*4;
    float4 v = ((const float4*)f2)[o4];
    int4 mm = *(const int4*)(g_idx + b*P2 + p);
    float* vv = (float*)&v;
    int mmv[4] = {mm.x, mm.y, mm.z, mm.w};
    #pragma unroll
    for (int j = 0; j < 4; j++) {
        int m = mmv[j];
        if (m >= 0) {
            int a = (b*NM + m)*C2 + c;
            vv[j] += g_mf0[a] + g_scale[b*NM + m]*g_gp[a];
        }
    }
    out4[i4] = v;
}

extern "C" void kernel_launch(void* const* d_in, const int* in_sizes, int n_in,
                              void* d_out, int out_size) {
    // Resolve inputs by unique element counts (robust to metadata ordering).
    const float* f0 = 0; const float* f1 = 0; const float* f2 = 0;
    const int* sam = 0; const float* W2 = 0; const float* b2 = 0;
    const float* g2 = 0;
    for (int i = 0; i < n_in; i++) {
        switch (in_sizes[i]) {
            case 16777216: f0  = (const float*)d_in[i]; break;  // 4*256*128*128
            case 8388608:  f1  = (const float*)d_in[i]; break;  // 4*512*64*64
            case 4194304:  f2  = (const float*)d_in[i]; break;  // 4*1024*32*32
            case 34603008: sam = (const int*)d_in[i];   break;  // 4*33*512*512
            case 1048576:  W2  = (const float*)d_in[i]; break;  // 1024*1024
            case 1024:     b2  = (const float*)d_in[i]; break;  // bias2
            case 1: if (!g2) g2 = (const float*)d_in[i]; break; // gates all equal
            default: break;
        }
    }
    float* out = (float*)d_out;

    k_idx    <<<dim3(NB,32), 1024>>>(sam);
    k_mfpart <<<dim3(NB,4,4), 256>>>(f2);
    k_mf0    <<<dim3(NB,NM), 256>>>();
    k_qgemm  <<<dim3(NB,8,KS), 256>>>(W2);
    k_qreduce<<<dim3(NB,NM), 256>>>(b2);
    k_simedge<<<dim3(NB,NM), 256>>>();
    k_gp     <<<dim3(NB,4), 256>>>();
    k_scale  <<<1, 128>>>(g2);
    k_final  <<<(unsigned)(TOT4/256), 256>>>(f0, f1, f2, out);
}